// round 16
// baseline (speedup 1.0000x reference)
#include <cuda_runtime.h>
#include <cuda_bf16.h>
#include <cstdint>

#define BATCH   64
#define CIN     3
#define LEN     100
#define FILTERS 64
#define L1      98
#define L2S     96
#define L3      94
#define KFC1    (FILTERS * L3)   // 6016
#define HID     10000
#define KP1     6016
#define KP2     10048
#define EPSB    1e-5f

__device__ __align__(16) float g_h1[BATCH * FILTERS * L1];
__device__ __align__(16) float g_h2[BATCH * FILTERS * L2S];
__device__ __align__(16) float g_h3[BATCH * FILTERS * L3];
__device__ __align__(16) float g_h5[BATCH * HID];
__device__ __align__(16) float g_p0[BATCH * HID];
__device__ __align__(16) float g_p1[BATCH * HID];
__device__ __align__(16) __nv_bfloat16 g_ahi[BATCH * KP2];   // zero-init padding
__device__ __align__(16) __nv_bfloat16 g_alo[BATCH * KP2];
__device__ float g_sc[HID];
__device__ float g_sh[HID];
__device__ float g_ps[BATCH * FILTERS];
__device__ float g_pss[BATCH * FILTERS];
__device__ float g_z[BATCH * 32];

__constant__ int c_rows[30] = {
      0,    1,   33,   66,   99,  200,  201,  233,  266,  299,
    800,  801,  833,  866,  899, 1000, 1001, 1033, 1066, 1099,
    300,  301,  333,  366,  399, 1100, 1101, 1133, 1166, 1199};
__constant__ int c_inv[12] = {0, -1, 1, 4, -1, -2, -1, -1, 2, -1, 3, 5};

__device__ __forceinline__ const float* hbuf(int id) {
    switch (id) { case 1: return g_h1; case 2: return g_h2; default: return g_h3; }
}
__device__ __forceinline__ float* hbufw(int id) {
    switch (id) { case 1: return g_h1; case 2: return g_h2; default: return g_h3; }
}

// ---------------- helpers -----------------------------------------------------
__device__ __forceinline__ uint32_t smem_u32(const void* p) {
    uint32_t a;
    asm("{ .reg .u64 t; cvta.to.shared.u64 t, %1; cvt.u32.u64 %0, t; }" : "=r"(a) : "l"(p));
    return a;
}
__device__ __forceinline__ void mma16816(float* d, const uint32_t* a, uint32_t b0, uint32_t b1) {
    asm volatile("mma.sync.aligned.m16n8k16.row.col.f32.bf16.bf16.f32 "
        "{%0,%1,%2,%3}, {%4,%5,%6,%7}, {%8,%9}, {%0,%1,%2,%3};"
        : "+f"(d[0]), "+f"(d[1]), "+f"(d[2]), "+f"(d[3])
        : "r"(a[0]), "r"(a[1]), "r"(a[2]), "r"(a[3]), "r"(b0), "r"(b1));
}
__device__ __forceinline__ void ldsm4(uint32_t* r, uint32_t addr) {
    asm volatile("ldmatrix.sync.aligned.m8n8.x4.shared.b16 {%0,%1,%2,%3}, [%4];"
        : "=r"(r[0]), "=r"(r[1]), "=r"(r[2]), "=r"(r[3]) : "r"(addr));
}
__device__ __forceinline__ void ldsm2(uint32_t* r, uint32_t addr) {
    asm volatile("ldmatrix.sync.aligned.m8n8.x2.shared.b16 {%0,%1}, [%2];"
        : "=r"(r[0]), "=r"(r[1]) : "r"(addr));
}
__device__ __forceinline__ void cvt_pair2(float x, float y, unsigned& uh, unsigned& ul) {
    unsigned ux = __float_as_uint(x), uy = __float_as_uint(y);
    uh = __byte_perm(ux, uy, 0x7632);
    float lx = x - __uint_as_float(ux & 0xFFFF0000u);
    float ly = y - __uint_as_float(uy & 0xFFFF0000u);
    __nv_bfloat162 l2 = __floats2bfloat162_rn(lx, ly);
    ul = *reinterpret_cast<unsigned*>(&l2);
}
__device__ __forceinline__ void split1(float x, __nv_bfloat16& h, __nv_bfloat16& l) {
    unsigned u = __float_as_uint(x);
    __nv_bfloat16_raw hr; hr.x = (unsigned short)(u >> 16);
    h = hr;
    l = __float2bfloat16_rn(x - __uint_as_float(u & 0xFFFF0000u));
}

// ---------------- conv1 (fused stats partials) ---------------------------------
__global__ __launch_bounds__(256) void conv1_k(const float* __restrict__ x,
                                               const float* __restrict__ w,
                                               const float* __restrict__ b) {
    __shared__ float sx[CIN * LEN];
    __shared__ float sw[FILTERS * 9];
    __shared__ float sb[FILTERS];
    int bi = blockIdx.x, tid = threadIdx.x;
    for (int i = tid; i < CIN * LEN; i += 256) sx[i] = x[bi * CIN * LEN + i];
    for (int i = tid; i < FILTERS * 9; i += 256) sw[i] = w[i];
    for (int i = tid; i < FILTERS; i += 256) sb[i] = b[i];
    __syncthreads();
    int c = tid >> 2, q = tid & 3;
    float wr[9];
    #pragma unroll
    for (int t = 0; t < 9; t++) wr[t] = sw[c * 9 + t];
    float bv = sb[c];
    float s = 0.f, ss = 0.f;
    int p0 = q * 25, p1 = p0 + 25; if (p1 > L1) p1 = L1;
    for (int p = p0; p < p1; p++) {
        float acc = bv
            + sx[p] * wr[0] + sx[p + 1] * wr[1] + sx[p + 2] * wr[2]
            + sx[100 + p] * wr[3] + sx[101 + p] * wr[4] + sx[102 + p] * wr[5]
            + sx[200 + p] * wr[6] + sx[201 + p] * wr[7] + sx[202 + p] * wr[8];
        float r = fmaxf(acc, 0.f);
        g_h1[(bi * FILTERS + c) * L1 + p] = r;
        s += r; ss += r * r;
    }
    s  += __shfl_xor_sync(~0u, s, 1);  s  += __shfl_xor_sync(~0u, s, 2);
    ss += __shfl_xor_sync(~0u, ss, 1); ss += __shfl_xor_sync(~0u, ss, 2);
    if (q == 0) { g_ps[bi * 64 + c] = s; g_pss[bi * 64 + c] = ss; }
}

// ---------------- conv2/3: fused input-BN (from partials) + stats partials -----
__global__ __launch_bounds__(256) void conv_k(int inId, int outId, int Lin, float Pst,
                                              const float* __restrict__ w,
                                              const float* __restrict__ bias,
                                              const float* __restrict__ bng,
                                              const float* __restrict__ bnb) {
    const float* in = hbuf(inId);
    float* out = hbufw(outId);
    int Lout = Lin - 2;
    int b = blockIdx.x, cog = blockIdx.y;
    __shared__ float sin_[FILTERS * L1];
    __shared__ float sw[8 * FILTERS * 3];
    __shared__ float red1[4][64], red2[4][64];
    __shared__ float sSc[64], sSh[64];
    int tid = threadIdx.x;
    {
        int cc = tid & 63, mg = tid >> 6;
        float s = 0.f, ss = 0.f;
        #pragma unroll 4
        for (int m = mg * 16; m < mg * 16 + 16; m++) {
            s += g_ps[m * 64 + cc];
            ss += g_pss[m * 64 + cc];
        }
        red1[mg][cc] = s; red2[mg][cc] = ss;
        __syncthreads();
        if (tid < 64) {
            float S = red1[0][tid] + red1[1][tid] + red1[2][tid] + red1[3][tid];
            float SS = red2[0][tid] + red2[1][tid] + red2[2][tid] + red2[3][tid];
            float inv = 1.f / (64.f * Pst);
            float mean = S * inv;
            float var = SS * inv - mean * mean;
            float sc = bng[tid] * rsqrtf(var + EPSB);
            sSc[tid] = sc;
            sSh[tid] = bnb[tid] - mean * sc;
        }
    }
    for (int i = tid; i < 8 * FILTERS * 3; i += 256)
        sw[i] = w[cog * 8 * FILTERS * 3 + i];
    __syncthreads();
    for (int i = tid; i < FILTERS * Lin; i += 256) {
        int ci = i / Lin;
        sin_[i] = in[(b * FILTERS + ci) * Lin + (i - ci * Lin)] * sSc[ci] + sSh[ci];
    }
    __syncthreads();
    int col = tid >> 5, lane = tid & 31;
    int co = cog * 8 + col;
    float bv = bias[co];
    float a0 = bv, a1 = bv, a2 = bv;
    const float* wc = &sw[col * 192];
    #pragma unroll 4
    for (int ci = 0; ci < FILTERS; ci++) {
        float w0 = wc[ci * 3], w1 = wc[ci * 3 + 1], w2 = wc[ci * 3 + 2];
        const float* r0 = &sin_[ci * Lin + lane];
        a0 += r0[0] * w0 + r0[1] * w1 + r0[2] * w2;
        a1 += r0[32] * w0 + r0[33] * w1 + r0[34] * w2;
        if (lane + 64 < Lin - 1) a2 += r0[64] * w0 + r0[65] * w1 + r0[66] * w2;
    }
    float s = 0.f, ss = 0.f, rv;
    rv = fmaxf(a0, 0.f); out[(b * FILTERS + co) * Lout + lane] = rv; s += rv; ss += rv * rv;
    rv = fmaxf(a1, 0.f); out[(b * FILTERS + co) * Lout + lane + 32] = rv; s += rv; ss += rv * rv;
    if (lane + 64 < Lout) {
        rv = fmaxf(a2, 0.f); out[(b * FILTERS + co) * Lout + lane + 64] = rv; s += rv; ss += rv * rv;
    }
    for (int o = 16; o > 0; o >>= 1) {
        s += __shfl_xor_sync(~0u, s, o);
        ss += __shfl_xor_sync(~0u, ss, o);
    }
    if (lane == 0) { g_ps[b * 64 + co] = s; g_pss[b * 64 + co] = ss; }
}

// ---------------- prep3: bn3 (from partials) + bf16 hi/lo split of h3 ----------
__global__ __launch_bounds__(256) void prep3_k(const float* __restrict__ bng,
                                               const float* __restrict__ bnb) {
    __shared__ float red1[4][64], red2[4][64];
    __shared__ float sSc[64], sSh[64];
    int m = blockIdx.x, qr = blockIdx.y, tid = threadIdx.x;
    {
        int cc = tid & 63, mg = tid >> 6;
        float s = 0.f, ss = 0.f;
        #pragma unroll 4
        for (int mm = mg * 16; mm < mg * 16 + 16; mm++) {
            s += g_ps[mm * 64 + cc];
            ss += g_pss[mm * 64 + cc];
        }
        red1[mg][cc] = s; red2[mg][cc] = ss;
        __syncthreads();
        if (tid < 64) {
            float S = red1[0][tid] + red1[1][tid] + red1[2][tid] + red1[3][tid];
            float SS = red2[0][tid] + red2[1][tid] + red2[2][tid] + red2[3][tid];
            float inv = 1.f / (64.f * (float)L3);
            float mean = S * inv;
            float var = SS * inv - mean * mean;
            float sc = bng[tid] * rsqrtf(var + EPSB);
            sSc[tid] = sc;
            sSh[tid] = bnb[tid] - mean * sc;
        }
    }
    __syncthreads();
    int i0 = qr * 752, i1 = i0 + 752;
    for (int i = i0 + tid; i < i1; i += 256) {
        int c = i / 94;
        float v = g_h3[m * KFC1 + i] * sSc[c] + sSh[c];
        __nv_bfloat16 h, l;
        split1(v, h, l);
        g_ahi[m * KP1 + i] = h;
        g_alo[m * KP1 + i] = l;
    }
}

// ---------------- tensor-core GEMM: M=64 x N=80, K chunks of 80, K-split x2 ----
// 10 warps (2 m-groups x 5 n-groups), 2 CTA/SM, pre-split bf16 A via cp.async,
// W fp32 -> bf16 hi/lo in-kernel. Chunk = 5 k16-steps: steps 0-3 via x4 B ldsm,
// step 4 (k64-79) via x2 B ldsm at +128. GP=176 (16x11, conflict-free).
#define GP    176
#define A_HIO 0
#define A_LOO 11264
#define W_HIO 22528
#define W_LOO 36608
#define STG   50688
__global__ __launch_bounds__(320, 2) void gemm_tc(const float* __restrict__ W,
                                                  int K, int KPa, int nChTot) {
    extern __shared__ char sm[];
    const int tid = threadIdx.x, lane = tid & 31, warp = tid >> 5;
    const int wm = warp & 1, wn = warp >> 1;
    const int nBase = blockIdx.x * 80;
    const int half = (nChTot + 1) >> 1;
    const int c0 = blockIdx.y * half;
    int c1 = c0 + half; if (c1 > nChTot) c1 = nChTot;
    float* outP = blockIdx.y ? g_p1 : g_p0;
    const uint32_t sb = smem_u32(sm);

    const int r_ = tid >> 2, wkq = (tid & 3) * 20;   // W: row, 20 k per thread
    const float* Wrow = W + (long)(nBase + r_) * K;  // r_<80, grid exact

    float4 fw[5];
    auto loadW = [&](int c) {
        int kb = c * 80 + wkq;
        #pragma unroll
        for (int j = 0; j < 5; j++) {
            int kg = kb + j * 4;
            if (kg + 3 < K) fw[j] = __ldg((const float4*)(Wrow + kg));
            else {
                float t[4];
                #pragma unroll
                for (int e = 0; e < 4; e++) t[e] = (kg + e < K) ? Wrow[kg + e] : 0.f;
                fw[j] = make_float4(t[0], t[1], t[2], t[3]);
            }
        }
    };
    auto storeW = [&](int s) {
        char* st = sm + s * STG;
        #pragma unroll
        for (int j = 0; j < 5; j++) {
            unsigned h0, l0, h1, l1;
            cvt_pair2(fw[j].x, fw[j].y, h0, l0);
            cvt_pair2(fw[j].z, fw[j].w, h1, l1);
            int off = r_ * GP + (wkq + j * 4) * 2;
            *(uint2*)(st + W_HIO + off) = make_uint2(h0, h1);
            *(uint2*)(st + W_LOO + off) = make_uint2(l0, l1);
        }
    };
    auto issueA = [&](int c, int s) {
        uint32_t dstb = sb + (uint32_t)(s * STG);
        int k0 = c * 80;
        #pragma unroll
        for (int p = 0; p < 4; p++) {
            int i = tid + p * 320;               // 1280 segments of 16B, exact
            int buf = (i >= 640) ? 1 : 0;
            int rem = i - buf * 640;
            int row = rem / 10, seg = rem - row * 10;
            const __nv_bfloat16* src =
                (buf ? g_alo : g_ahi) + (long)row * KPa + k0 + seg * 8;
            uint32_t dst = dstb + (buf ? A_LOO : A_HIO) + row * GP + seg * 16;
            asm volatile("cp.async.ca.shared.global [%0], [%1], 16;"
                         :: "r"(dst), "l"(src));
        }
        asm volatile("cp.async.commit_group;" ::: "memory");
    };

    const uint32_t aOff  = (uint32_t)((wm * 32 + (lane & 15)) * GP + (lane >> 4) * 16);
    const uint32_t bOff  = (uint32_t)((wn * 16 + (lane & 7)) * GP + (lane >> 3) * 16);
    const uint32_t bOff2 = (uint32_t)((wn * 16 + (lane & 7)) * GP + ((lane >> 3) & 1) * 16);
    float acc[2][2][4] = {};

    issueA(c0, 0);
    loadW(c0);
    storeW(0);
    asm volatile("cp.async.wait_group 0;" ::: "memory");
    __syncthreads();

    for (int c = c0; c < c1; c++) {
        int s = (c - c0) & 1;
        if (c + 1 < c1) { issueA(c + 1, s ^ 1); loadW(c + 1); }
        const uint32_t stb = sb + (uint32_t)(s * STG);
        #pragma unroll
        for (int kh = 0; kh < 2; kh++) {         // k-steps 0-3 (k0-63)
            uint32_t bhf[2][4], blf[2][4];
            #pragma unroll
            for (int nt = 0; nt < 2; nt++) {
                ldsm4(bhf[nt], stb + W_HIO + nt * 8 * GP + bOff + kh * 64);
                ldsm4(blf[nt], stb + W_LOO + nt * 8 * GP + bOff + kh * 64);
            }
            #pragma unroll
            for (int kk = 0; kk < 2; kk++) {
                int ks = kh * 2 + kk;
                #pragma unroll
                for (int mt = 0; mt < 2; mt++) {
                    uint32_t ah[4], al[4];
                    ldsm4(ah, stb + A_HIO + aOff + mt * 16 * GP + ks * 32);
                    ldsm4(al, stb + A_LOO + aOff + mt * 16 * GP + ks * 32);
                    #pragma unroll
                    for (int nt = 0; nt < 2; nt++) {
                        mma16816(acc[mt][nt], ah, bhf[nt][kk * 2], bhf[nt][kk * 2 + 1]);
                        mma16816(acc[mt][nt], ah, blf[nt][kk * 2], blf[nt][kk * 2 + 1]);
                        mma16816(acc[mt][nt], al, bhf[nt][kk * 2], bhf[nt][kk * 2 + 1]);
                    }
                }
            }
        }
        {   // tail k-step 4 (k64-79): B via x2 ldsm, A via x4 at +128
            uint32_t bh2[2][2], bl2[2][2];
            #pragma unroll
            for (int nt = 0; nt < 2; nt++) {
                ldsm2(bh2[nt], stb + W_HIO + nt * 8 * GP + bOff2 + 128);
                ldsm2(bl2[nt], stb + W_LOO + nt * 8 * GP + bOff2 + 128);
            }
            #pragma unroll
            for (int mt = 0; mt < 2; mt++) {
                uint32_t ah[4], al[4];
                ldsm4(ah, stb + A_HIO + aOff + mt * 16 * GP + 128);
                ldsm4(al, stb + A_LOO + aOff + mt * 16 * GP + 128);
                #pragma unroll
                for (int nt = 0; nt < 2; nt++) {
                    mma16816(acc[mt][nt], ah, bh2[nt][0], bh2[nt][1]);
                    mma16816(acc[mt][nt], ah, bl2[nt][0], bl2[nt][1]);
                    mma16816(acc[mt][nt], al, bh2[nt][0], bh2[nt][1]);
                }
            }
        }
        if (c + 1 < c1) storeW(s ^ 1);
        asm volatile("cp.async.wait_group 0;" ::: "memory");
        __syncthreads();
    }

    #pragma unroll
    for (int mt = 0; mt < 2; mt++) {
        int m = wm * 32 + mt * 16 + (lane >> 2);
        #pragma unroll
        for (int nt = 0; nt < 2; nt++) {
            int n0 = nBase + wn * 16 + nt * 8 + (lane & 3) * 2;
            #pragma unroll
            for (int h = 0; h < 2; h++)
                *(float2*)(outP + (long)(m + h * 8) * HID + n0) =
                    make_float2(acc[mt][nt][h * 2], acc[mt][nt][h * 2 + 1]);
        }
    }
}

// ---------------- comb4: sum halves + bias + relu + bn4 + split for fc2 --------
__global__ __launch_bounds__(256) void comb4_k(const float* __restrict__ bias,
                                               const float* __restrict__ g,
                                               const float* __restrict__ be) {
    __shared__ float r1[4][64], r2[4][64], sSc[64], sSh[64], sBv[64];
    int tid = threadIdx.x;
    int jt = blockIdx.x * 64;
    int jl = tid & 63, mg = tid >> 6;
    int j = jt + jl;
    bool ok = j < HID;
    if (mg == 0) sBv[jl] = ok ? bias[j] : 0.f;
    __syncthreads();
    float bv = sBv[jl];
    float s = 0.f, ss = 0.f;
    #pragma unroll 4
    for (int m = mg * 16; m < mg * 16 + 16; m++) {
        float v = ok ? fmaxf(g_p0[m * HID + j] + g_p1[m * HID + j] + bv, 0.f) : 0.f;
        s += v; ss += v * v;
    }
    r1[mg][jl] = s; r2[mg][jl] = ss;
    __syncthreads();
    if (tid < 64) {
        float S = r1[0][tid] + r1[1][tid] + r1[2][tid] + r1[3][tid];
        float SS = r2[0][tid] + r2[1][tid] + r2[2][tid] + r2[3][tid];
        float mean = S * (1.f / 64.f);
        float var = SS * (1.f / 64.f) - mean * mean;
        float sc = g[jt + tid < HID ? jt + tid : 0] * rsqrtf(var + EPSB);
        sSc[tid] = sc;
        sSh[tid] = (jt + tid < HID ? be[jt + tid] : 0.f) - mean * sc;
    }
    __syncthreads();
    if (!ok) return;
    float sc = sSc[jl], sh = sSh[jl];
    #pragma unroll 4
    for (int m = mg * 16; m < mg * 16 + 16; m++) {
        float v = fmaxf(g_p0[m * HID + j] + g_p1[m * HID + j] + bv, 0.f) * sc + sh;
        __nv_bfloat16 h, l;
        split1(v, h, l);
        g_ahi[m * KP2 + j] = h;
        g_alo[m * KP2 + j] = l;
    }
}

// ---------------- comb5: sum halves + bias + relu + bn5 stats -------------------
__global__ __launch_bounds__(256) void comb5_k(const float* __restrict__ bias,
                                               const float* __restrict__ g,
                                               const float* __restrict__ be) {
    __shared__ float r1[4][64], r2[4][64], sBv[64];
    int tid = threadIdx.x;
    int jt = blockIdx.x * 64;
    int jl = tid & 63, mg = tid >> 6;
    int j = jt + jl;
    bool ok = j < HID;
    if (mg == 0) sBv[jl] = ok ? bias[j] : 0.f;
    __syncthreads();
    float bv = sBv[jl];
    float s = 0.f, ss = 0.f;
    #pragma unroll 4
    for (int m = mg * 16; m < mg * 16 + 16; m++) {
        float v = ok ? fmaxf(g_p0[m * HID + j] + g_p1[m * HID + j] + bv, 0.f) : 0.f;
        if (ok) g_h5[m * HID + j] = v;
        s += v; ss += v * v;
    }
    r1[mg][jl] = s; r2[mg][jl] = ss;
    __syncthreads();
    if (tid < 64 && jt + tid < HID) {
        float S = r1[0][tid] + r1[1][tid] + r1[2][tid] + r1[3][tid];
        float SS = r2[0][tid] + r2[1][tid] + r2[2][tid] + r2[3][tid];
        float mean = S * (1.f / 64.f);
        float var = SS * (1.f / 64.f) - mean * mean;
        float sc = g[jt + tid] * rsqrtf(var + EPSB);
        g_sc[jt + tid] = sc;
        g_sh[jt + tid] = be[jt + tid] - mean * sc;
    }
}

// ---------------- fc3: 30 observable rows x 64 batches --------------------------
__global__ void fc3_k(const float* __restrict__ w, const float* __restrict__ b) {
    int rr = blockIdx.x, bg = blockIdx.y;
    int row = c_rows[rr];
    const float* wr = &w[(long)row * HID];
    int tid = threadIdx.x;
    float acc[8] = {};
    for (int i = tid; i < HID; i += 256) {
        float wv = wr[i];
        float scw = g_sc[i] * wv, shw = g_sh[i] * wv;
        #pragma unroll
        for (int bb = 0; bb < 8; bb++)
            acc[bb] += g_h5[(bg * 8 + bb) * HID + i] * scw + shw;
    }
    __shared__ float red[8][8];
    int lane = tid & 31, wp = tid >> 5;
    #pragma unroll
    for (int bb = 0; bb < 8; bb++) {
        float v = acc[bb];
        for (int o = 16; o > 0; o >>= 1) v += __shfl_down_sync(~0u, v, o);
        if (lane == 0) red[bb][wp] = v;
    }
    __syncthreads();
    if (tid < 8) {
        float v = 0.f;
        #pragma unroll
        for (int wpp = 0; wpp < 8; wpp++) v += red[tid][wpp];
        g_z[(bg * 8 + tid) * 30 + rr] = v + b[row];
    }
}

// ---------------- epilogue -------------------------------------------------------
__global__ void epilogue_k(float* __restrict__ out) {
    int idx = blockIdx.x * blockDim.x + threadIdx.x;
    if (idx >= BATCH * 12 * LEN) return;
    int b = idx / (12 * LEN);
    int rem = idx - b * 12 * LEN;
    int ch = rem / LEN;
    int p = rem - ch * LEN;
    int code = c_inv[ch];
    float v;
    if (code == -1) v = 0.f;
    else if (code == -2) v = 1.f;
    else {
        const float* z = &g_z[b * 30 + code * 5];
        if (p == 0) v = z[0];
        else if (p == 1) v = z[1];
        else if (p == 33) v = z[2];
        else if (p == 66) v = z[3];
        else if (p == 99) v = z[4];
        else {
            int j = p / 33;
            const int cl[3] = {1, 33, 66};
            float alpha = (float)(p - cl[j]) / 33.f;
            v = alpha * z[j + 1] + (1.f - alpha) * z[j + 2];
        }
    }
    out[idx] = v;
}

// ---------------- launcher ---------------------------------------------------------
extern "C" void kernel_launch(void* const* d_in, const int* in_sizes, int n_in,
                              void* d_out, int out_size) {
    const float* x       = (const float*)d_in[0];
    const float* conv1_w = (const float*)d_in[1];
    const float* conv1_b = (const float*)d_in[2];
    const float* bn1_g   = (const float*)d_in[3];
    const float* bn1_b   = (const float*)d_in[4];
    const float* conv2_w = (const float*)d_in[5];
    const float* conv2_b = (const float*)d_in[6];
    const float* bn2_g   = (const float*)d_in[7];
    const float* bn2_b   = (const float*)d_in[8];
    const float* conv3_w = (const float*)d_in[9];
    const float* conv3_b = (const float*)d_in[10];
    const float* bn3_g   = (const float*)d_in[11];
    const float* bn3_b   = (const float*)d_in[12];
    const float* fc1_w   = (const float*)d_in[13];
    const float* fc1_b   = (const float*)d_in[14];
    const float* bn4_g   = (const float*)d_in[15];
    const float* bn4_b   = (const float*)d_in[16];
    const float* fc2_w   = (const float*)d_in[17];
    const float* fc2_b   = (const float*)d_in[18];
    const float* bn5_g   = (const float*)d_in[19];
    const float* bn5_b   = (const float*)d_in[20];
    const float* fc3_w   = (const float*)d_in[21];
    const float* fc3_b   = (const float*)d_in[22];
    float* out = (float*)d_out;

    cudaFuncSetAttribute(gemm_tc, cudaFuncAttributeMaxDynamicSharedMemorySize, 2 * STG);

    conv1_k<<<BATCH, 256>>>(x, conv1_w, conv1_b);                                   // 1
    conv_k<<<dim3(BATCH, 8), 256>>>(1, 2, L1, (float)L1, conv2_w, conv2_b,
                                    bn1_g, bn1_b);                                  // 2
    conv_k<<<dim3(BATCH, 8), 256>>>(2, 3, L2S, (float)L2S, conv3_w, conv3_b,
                                    bn2_g, bn2_b);                                  // 3
    prep3_k<<<dim3(BATCH, 8), 256>>>(bn3_g, bn3_b);                                 // 4
    gemm_tc<<<dim3(125, 2), 320, 2 * STG>>>(fc1_w, KFC1, KP1, 76);                  // 5
    comb4_k<<<157, 256>>>(fc1_b, bn4_g, bn4_b);                                     // 6
    gemm_tc<<<dim3(125, 2), 320, 2 * STG>>>(fc2_w, HID, KP2, 125);                  // 7
    comb5_k<<<157, 256>>>(fc2_b, bn5_g, bn5_b);                                     // 8
    fc3_k<<<dim3(30, 8), 256>>>(fc3_w, fc3_b);                                      // 9
    epilogue_k<<<(BATCH * 12 * LEN + 255) / 256, 256>>>(out);                       // 10
}

// round 17
// speedup vs baseline: 1.3468x; 1.3468x over previous
#include <cuda_runtime.h>
#include <cuda_bf16.h>
#include <cstdint>

#define BATCH   64
#define CIN     3
#define LEN     100
#define FILTERS 64
#define L1      98
#define L2S     96
#define L3      94
#define KFC1    (FILTERS * L3)   // 6016
#define HID     10000
#define KP1     6016
#define KP2     10048
#define EPSB    1e-5f

__device__ __align__(16) float g_h1[BATCH * FILTERS * L1];
__device__ __align__(16) float g_h2[BATCH * FILTERS * L2S];
__device__ __align__(16) float g_h3[BATCH * FILTERS * L3];
__device__ __align__(16) float g_h5[BATCH * HID];
__device__ __align__(16) float g_p0[BATCH * HID];
__device__ __align__(16) float g_p1[BATCH * HID];
__device__ __align__(16) __nv_bfloat16 g_ahi[BATCH * KP2];   // zero-init padding
__device__ __align__(16) __nv_bfloat16 g_alo[BATCH * KP2];
__device__ float g_sc[HID];
__device__ float g_sh[HID];
__device__ float g_ps[BATCH * FILTERS];
__device__ float g_pss[BATCH * FILTERS];
__device__ float g_z[BATCH * 32];

__constant__ int c_rows[30] = {
      0,    1,   33,   66,   99,  200,  201,  233,  266,  299,
    800,  801,  833,  866,  899, 1000, 1001, 1033, 1066, 1099,
    300,  301,  333,  366,  399, 1100, 1101, 1133, 1166, 1199};
__constant__ int c_inv[12] = {0, -1, 1, 4, -1, -2, -1, -1, 2, -1, 3, 5};

__device__ __forceinline__ const float* hbuf(int id) {
    switch (id) { case 1: return g_h1; case 2: return g_h2; default: return g_h3; }
}
__device__ __forceinline__ float* hbufw(int id) {
    switch (id) { case 1: return g_h1; case 2: return g_h2; default: return g_h3; }
}

// ---------------- helpers -----------------------------------------------------
__device__ __forceinline__ uint32_t smem_u32(const void* p) {
    uint32_t a;
    asm("{ .reg .u64 t; cvta.to.shared.u64 t, %1; cvt.u32.u64 %0, t; }" : "=r"(a) : "l"(p));
    return a;
}
__device__ __forceinline__ void mma16816(float* d, const uint32_t* a, uint32_t b0, uint32_t b1) {
    asm volatile("mma.sync.aligned.m16n8k16.row.col.f32.bf16.bf16.f32 "
        "{%0,%1,%2,%3}, {%4,%5,%6,%7}, {%8,%9}, {%0,%1,%2,%3};"
        : "+f"(d[0]), "+f"(d[1]), "+f"(d[2]), "+f"(d[3])
        : "r"(a[0]), "r"(a[1]), "r"(a[2]), "r"(a[3]), "r"(b0), "r"(b1));
}
__device__ __forceinline__ void ldsm4(uint32_t* r, uint32_t addr) {
    asm volatile("ldmatrix.sync.aligned.m8n8.x4.shared.b16 {%0,%1,%2,%3}, [%4];"
        : "=r"(r[0]), "=r"(r[1]), "=r"(r[2]), "=r"(r[3]) : "r"(addr));
}
__device__ __forceinline__ void cvt_pair2(float x, float y, unsigned& uh, unsigned& ul) {
    unsigned ux = __float_as_uint(x), uy = __float_as_uint(y);
    uh = __byte_perm(ux, uy, 0x7632);
    float lx = x - __uint_as_float(ux & 0xFFFF0000u);
    float ly = y - __uint_as_float(uy & 0xFFFF0000u);
    __nv_bfloat162 l2 = __floats2bfloat162_rn(lx, ly);
    ul = *reinterpret_cast<unsigned*>(&l2);
}
__device__ __forceinline__ void split1(float x, __nv_bfloat16& h, __nv_bfloat16& l) {
    unsigned u = __float_as_uint(x);
    __nv_bfloat16_raw hr; hr.x = (unsigned short)(u >> 16);
    h = hr;
    l = __float2bfloat16_rn(x - __uint_as_float(u & 0xFFFF0000u));
}

// ---------------- conv1 (fused stats partials) ---------------------------------
__global__ __launch_bounds__(256) void conv1_k(const float* __restrict__ x,
                                               const float* __restrict__ w,
                                               const float* __restrict__ b) {
    __shared__ float sx[CIN * LEN];
    __shared__ float sw[FILTERS * 9];
    __shared__ float sb[FILTERS];
    int bi = blockIdx.x, tid = threadIdx.x;
    for (int i = tid; i < CIN * LEN; i += 256) sx[i] = x[bi * CIN * LEN + i];
    for (int i = tid; i < FILTERS * 9; i += 256) sw[i] = w[i];
    for (int i = tid; i < FILTERS; i += 256) sb[i] = b[i];
    __syncthreads();
    int c = tid >> 2, q = tid & 3;
    float wr[9];
    #pragma unroll
    for (int t = 0; t < 9; t++) wr[t] = sw[c * 9 + t];
    float bv = sb[c];
    float s = 0.f, ss = 0.f;
    int p0 = q * 25, p1 = p0 + 25; if (p1 > L1) p1 = L1;
    for (int p = p0; p < p1; p++) {
        float acc = bv
            + sx[p] * wr[0] + sx[p + 1] * wr[1] + sx[p + 2] * wr[2]
            + sx[100 + p] * wr[3] + sx[101 + p] * wr[4] + sx[102 + p] * wr[5]
            + sx[200 + p] * wr[6] + sx[201 + p] * wr[7] + sx[202 + p] * wr[8];
        float r = fmaxf(acc, 0.f);
        g_h1[(bi * FILTERS + c) * L1 + p] = r;
        s += r; ss += r * r;
    }
    s  += __shfl_xor_sync(~0u, s, 1);  s  += __shfl_xor_sync(~0u, s, 2);
    ss += __shfl_xor_sync(~0u, ss, 1); ss += __shfl_xor_sync(~0u, ss, 2);
    if (q == 0) { g_ps[bi * 64 + c] = s; g_pss[bi * 64 + c] = ss; }
}

// ---------------- conv2/3: fused input-BN (from partials) + stats partials -----
__global__ __launch_bounds__(256) void conv_k(int inId, int outId, int Lin, float Pst,
                                              const float* __restrict__ w,
                                              const float* __restrict__ bias,
                                              const float* __restrict__ bng,
                                              const float* __restrict__ bnb) {
    const float* in = hbuf(inId);
    float* out = hbufw(outId);
    int Lout = Lin - 2;
    int b = blockIdx.x, cog = blockIdx.y;
    __shared__ float sin_[FILTERS * L1];
    __shared__ float sw[8 * FILTERS * 3];
    __shared__ float red1[4][64], red2[4][64];
    __shared__ float sSc[64], sSh[64];
    int tid = threadIdx.x;
    {
        int cc = tid & 63, mg = tid >> 6;
        float s = 0.f, ss = 0.f;
        #pragma unroll 4
        for (int m = mg * 16; m < mg * 16 + 16; m++) {
            s += g_ps[m * 64 + cc];
            ss += g_pss[m * 64 + cc];
        }
        red1[mg][cc] = s; red2[mg][cc] = ss;
        __syncthreads();
        if (tid < 64) {
            float S = red1[0][tid] + red1[1][tid] + red1[2][tid] + red1[3][tid];
            float SS = red2[0][tid] + red2[1][tid] + red2[2][tid] + red2[3][tid];
            float inv = 1.f / (64.f * Pst);
            float mean = S * inv;
            float var = SS * inv - mean * mean;
            float sc = bng[tid] * rsqrtf(var + EPSB);
            sSc[tid] = sc;
            sSh[tid] = bnb[tid] - mean * sc;
        }
    }
    for (int i = tid; i < 8 * FILTERS * 3; i += 256)
        sw[i] = w[cog * 8 * FILTERS * 3 + i];
    __syncthreads();
    for (int i = tid; i < FILTERS * Lin; i += 256) {
        int ci = i / Lin;
        sin_[i] = in[(b * FILTERS + ci) * Lin + (i - ci * Lin)] * sSc[ci] + sSh[ci];
    }
    __syncthreads();
    int col = tid >> 5, lane = tid & 31;
    int co = cog * 8 + col;
    float bv = bias[co];
    float a0 = bv, a1 = bv, a2 = bv;
    const float* wc = &sw[col * 192];
    #pragma unroll 4
    for (int ci = 0; ci < FILTERS; ci++) {
        float w0 = wc[ci * 3], w1 = wc[ci * 3 + 1], w2 = wc[ci * 3 + 2];
        const float* r0 = &sin_[ci * Lin + lane];
        a0 += r0[0] * w0 + r0[1] * w1 + r0[2] * w2;
        a1 += r0[32] * w0 + r0[33] * w1 + r0[34] * w2;
        if (lane + 64 < Lin - 1) a2 += r0[64] * w0 + r0[65] * w1 + r0[66] * w2;
    }
    float s = 0.f, ss = 0.f, rv;
    rv = fmaxf(a0, 0.f); out[(b * FILTERS + co) * Lout + lane] = rv; s += rv; ss += rv * rv;
    rv = fmaxf(a1, 0.f); out[(b * FILTERS + co) * Lout + lane + 32] = rv; s += rv; ss += rv * rv;
    if (lane + 64 < Lout) {
        rv = fmaxf(a2, 0.f); out[(b * FILTERS + co) * Lout + lane + 64] = rv; s += rv; ss += rv * rv;
    }
    for (int o = 16; o > 0; o >>= 1) {
        s += __shfl_xor_sync(~0u, s, o);
        ss += __shfl_xor_sync(~0u, ss, o);
    }
    if (lane == 0) { g_ps[b * 64 + co] = s; g_pss[b * 64 + co] = ss; }
}

// ---------------- prep3: bn3 (from partials) + bf16 hi/lo split of h3 ----------
__global__ __launch_bounds__(256) void prep3_k(const float* __restrict__ bng,
                                               const float* __restrict__ bnb) {
    __shared__ float red1[4][64], red2[4][64];
    __shared__ float sSc[64], sSh[64];
    int m = blockIdx.x, qr = blockIdx.y, tid = threadIdx.x;
    {
        int cc = tid & 63, mg = tid >> 6;
        float s = 0.f, ss = 0.f;
        #pragma unroll 4
        for (int mm = mg * 16; mm < mg * 16 + 16; mm++) {
            s += g_ps[mm * 64 + cc];
            ss += g_pss[mm * 64 + cc];
        }
        red1[mg][cc] = s; red2[mg][cc] = ss;
        __syncthreads();
        if (tid < 64) {
            float S = red1[0][tid] + red1[1][tid] + red1[2][tid] + red1[3][tid];
            float SS = red2[0][tid] + red2[1][tid] + red2[2][tid] + red2[3][tid];
            float inv = 1.f / (64.f * (float)L3);
            float mean = S * inv;
            float var = SS * inv - mean * mean;
            float sc = bng[tid] * rsqrtf(var + EPSB);
            sSc[tid] = sc;
            sSh[tid] = bnb[tid] - mean * sc;
        }
    }
    __syncthreads();
    int i0 = qr * 752, i1 = i0 + 752;
    for (int i = i0 + tid; i < i1; i += 256) {
        int c = i / 94;
        float v = g_h3[m * KFC1 + i] * sSc[c] + sSh[c];
        __nv_bfloat16 h, l;
        split1(v, h, l);
        g_ahi[m * KP1 + i] = h;
        g_alo[m * KP1 + i] = l;
    }
}

// ---------------- tensor-core GEMM: M=64 x N=80, K chunks of 64, K-split x2 ----
// 10 warps (2 m-groups x 5 n-groups), 2 CTA/SM, pre-split bf16 A via cp.async,
// W fp32 -> bf16 hi/lo in-kernel. (Proven 390.8us configuration.)
#define GP    144
#define A_HIO 0
#define A_LOO 9216
#define W_HIO 18432
#define W_LOO 29952
#define STG   41472
__global__ __launch_bounds__(320, 2) void gemm_tc(const float* __restrict__ W,
                                                  int K, int KPa, int nChTot) {
    extern __shared__ char sm[];
    const int tid = threadIdx.x, lane = tid & 31, warp = tid >> 5;
    const int wm = warp & 1, wn = warp >> 1;
    const int nBase = blockIdx.x * 80;
    const int half = (nChTot + 1) >> 1;
    const int c0 = blockIdx.y * half;
    int c1 = c0 + half; if (c1 > nChTot) c1 = nChTot;
    float* outP = blockIdx.y ? g_p1 : g_p0;
    const uint32_t sb = smem_u32(sm);

    const int r_ = tid >> 2, wkq = (tid & 3) << 4;
    const float* Wrow = W + (long)(nBase + r_) * K;   // r_<80, grid exact

    float4 fw[4];
    auto loadW = [&](int c) {
        int kb = (c << 6) + wkq;
        #pragma unroll
        for (int j = 0; j < 4; j++) {
            int kg = kb + j * 4;
            if (kg + 3 < K) fw[j] = __ldg((const float4*)(Wrow + kg));
            else {
                float t[4];
                #pragma unroll
                for (int e = 0; e < 4; e++) t[e] = (kg + e < K) ? Wrow[kg + e] : 0.f;
                fw[j] = make_float4(t[0], t[1], t[2], t[3]);
            }
        }
    };
    auto storeW = [&](int s) {
        char* st = sm + s * STG;
        #pragma unroll
        for (int j = 0; j < 4; j++) {
            unsigned h0, l0, h1, l1;
            cvt_pair2(fw[j].x, fw[j].y, h0, l0);
            cvt_pair2(fw[j].z, fw[j].w, h1, l1);
            int off = r_ * GP + (wkq + j * 4) * 2;
            *(uint2*)(st + W_HIO + off) = make_uint2(h0, h1);
            *(uint2*)(st + W_LOO + off) = make_uint2(l0, l1);
        }
    };
    auto issueA = [&](int c, int s) {
        uint32_t dstb = sb + (uint32_t)(s * STG);
        int k0 = c << 6;
        #pragma unroll
        for (int p = 0; p < 4; p++) {
            int i = tid + p * 320;
            if (i < 1024) {
                int buf = i >> 9, rem = i & 511, row = rem >> 3, seg = rem & 7;
                const __nv_bfloat16* src =
                    (buf ? g_alo : g_ahi) + (long)row * KPa + k0 + seg * 8;
                uint32_t dst = dstb + (buf ? A_LOO : A_HIO) + row * GP + seg * 16;
                asm volatile("cp.async.ca.shared.global [%0], [%1], 16;"
                             :: "r"(dst), "l"(src));
            }
        }
        asm volatile("cp.async.commit_group;" ::: "memory");
    };

    const uint32_t aOff = (uint32_t)((wm * 32 + (lane & 15)) * GP + (lane >> 4) * 16);
    const uint32_t bOff = (uint32_t)((wn * 16 + (lane & 7)) * GP + (lane >> 3) * 16);
    float acc[2][2][4] = {};

    issueA(c0, 0);
    loadW(c0);
    storeW(0);
    asm volatile("cp.async.wait_group 0;" ::: "memory");
    __syncthreads();

    for (int c = c0; c < c1; c++) {
        int s = (c - c0) & 1;
        if (c + 1 < c1) { issueA(c + 1, s ^ 1); loadW(c + 1); }
        const uint32_t stb = sb + (uint32_t)(s * STG);
        #pragma unroll
        for (int kh = 0; kh < 2; kh++) {
            uint32_t bhf[2][4], blf[2][4];
            #pragma unroll
            for (int nt = 0; nt < 2; nt++) {
                ldsm4(bhf[nt], stb + W_HIO + nt * 8 * GP + bOff + kh * 64);
                ldsm4(blf[nt], stb + W_LOO + nt * 8 * GP + bOff + kh * 64);
            }
            #pragma unroll
            for (int kk = 0; kk < 2; kk++) {
                int ks = kh * 2 + kk;
                #pragma unroll
                for (int mt = 0; mt < 2; mt++) {
                    uint32_t ah[4], al[4];
                    ldsm4(ah, stb + A_HIO + aOff + mt * 16 * GP + ks * 32);
                    ldsm4(al, stb + A_LOO + aOff + mt * 16 * GP + ks * 32);
                    #pragma unroll
                    for (int nt = 0; nt < 2; nt++) {
                        mma16816(acc[mt][nt], ah, bhf[nt][kk * 2], bhf[nt][kk * 2 + 1]);
                        mma16816(acc[mt][nt], ah, blf[nt][kk * 2], blf[nt][kk * 2 + 1]);
                        mma16816(acc[mt][nt], al, bhf[nt][kk * 2], bhf[nt][kk * 2 + 1]);
                    }
                }
            }
        }
        if (c + 1 < c1) storeW(s ^ 1);
        asm volatile("cp.async.wait_group 0;" ::: "memory");
        __syncthreads();
    }

    #pragma unroll
    for (int mt = 0; mt < 2; mt++) {
        int m = wm * 32 + mt * 16 + (lane >> 2);
        #pragma unroll
        for (int nt = 0; nt < 2; nt++) {
            int n0 = nBase + wn * 16 + nt * 8 + (lane & 3) * 2;
            #pragma unroll
            for (int h = 0; h < 2; h++)
                *(float2*)(outP + (long)(m + h * 8) * HID + n0) =
                    make_float2(acc[mt][nt][h * 2], acc[mt][nt][h * 2 + 1]);
        }
    }
}

// ---------------- comb4: sum halves + bias + relu + bn4 + split for fc2 --------
// Partial sums register-cached (vv[16]) so g_p0/g_p1 are read exactly once.
__global__ __launch_bounds__(256) void comb4_k(const float* __restrict__ bias,
                                               const float* __restrict__ g,
                                               const float* __restrict__ be) {
    __shared__ float r1[4][64], r2[4][64], sSc[64], sSh[64], sBv[64];
    int tid = threadIdx.x;
    int jt = blockIdx.x * 64;
    int jl = tid & 63, mg = tid >> 6;
    int j = jt + jl;
    bool ok = j < HID;
    if (mg == 0) sBv[jl] = ok ? bias[j] : 0.f;
    __syncthreads();
    float bv = sBv[jl];
    float s = 0.f, ss = 0.f;
    float vv[16];
    #pragma unroll 4
    for (int t = 0; t < 16; t++) {
        int m = mg * 16 + t;
        float v = ok ? fmaxf(g_p0[m * HID + j] + g_p1[m * HID + j] + bv, 0.f) : 0.f;
        vv[t] = v;
        s += v; ss += v * v;
    }
    r1[mg][jl] = s; r2[mg][jl] = ss;
    __syncthreads();
    if (tid < 64) {
        float S = r1[0][tid] + r1[1][tid] + r1[2][tid] + r1[3][tid];
        float SS = r2[0][tid] + r2[1][tid] + r2[2][tid] + r2[3][tid];
        float mean = S * (1.f / 64.f);
        float var = SS * (1.f / 64.f) - mean * mean;
        float sc = g[jt + tid < HID ? jt + tid : 0] * rsqrtf(var + EPSB);
        sSc[tid] = sc;
        sSh[tid] = (jt + tid < HID ? be[jt + tid] : 0.f) - mean * sc;
    }
    __syncthreads();
    if (!ok) return;
    float sc = sSc[jl], sh = sSh[jl];
    #pragma unroll 4
    for (int t = 0; t < 16; t++) {
        int m = mg * 16 + t;
        float v = vv[t] * sc + sh;
        __nv_bfloat16 h, l;
        split1(v, h, l);
        g_ahi[m * KP2 + j] = h;
        g_alo[m * KP2 + j] = l;
    }
}

// ---------------- comb5: sum halves + bias + relu + bn5 stats -------------------
__global__ __launch_bounds__(256) void comb5_k(const float* __restrict__ bias,
                                               const float* __restrict__ g,
                                               const float* __restrict__ be) {
    __shared__ float r1[4][64], r2[4][64], sBv[64];
    int tid = threadIdx.x;
    int jt = blockIdx.x * 64;
    int jl = tid & 63, mg = tid >> 6;
    int j = jt + jl;
    bool ok = j < HID;
    if (mg == 0) sBv[jl] = ok ? bias[j] : 0.f;
    __syncthreads();
    float bv = sBv[jl];
    float s = 0.f, ss = 0.f;
    #pragma unroll 4
    for (int m = mg * 16; m < mg * 16 + 16; m++) {
        float v = ok ? fmaxf(g_p0[m * HID + j] + g_p1[m * HID + j] + bv, 0.f) : 0.f;
        if (ok) g_h5[m * HID + j] = v;
        s += v; ss += v * v;
    }
    r1[mg][jl] = s; r2[mg][jl] = ss;
    __syncthreads();
    if (tid < 64 && jt + tid < HID) {
        float S = r1[0][tid] + r1[1][tid] + r1[2][tid] + r1[3][tid];
        float SS = r2[0][tid] + r2[1][tid] + r2[2][tid] + r2[3][tid];
        float mean = S * (1.f / 64.f);
        float var = SS * (1.f / 64.f) - mean * mean;
        float sc = g[jt + tid] * rsqrtf(var + EPSB);
        g_sc[jt + tid] = sc;
        g_sh[jt + tid] = be[jt + tid] - mean * sc;
    }
}

// ---------------- fc3: 30 observable rows x 64 batches --------------------------
__global__ void fc3_k(const float* __restrict__ w, const float* __restrict__ b) {
    int rr = blockIdx.x, bg = blockIdx.y;
    int row = c_rows[rr];
    const float* wr = &w[(long)row * HID];
    int tid = threadIdx.x;
    float acc[8] = {};
    for (int i = tid; i < HID; i += 256) {
        float wv = wr[i];
        float scw = g_sc[i] * wv, shw = g_sh[i] * wv;
        #pragma unroll
        for (int bb = 0; bb < 8; bb++)
            acc[bb] += g_h5[(bg * 8 + bb) * HID + i] * scw + shw;
    }
    __shared__ float red[8][8];
    int lane = tid & 31, wp = tid >> 5;
    #pragma unroll
    for (int bb = 0; bb < 8; bb++) {
        float v = acc[bb];
        for (int o = 16; o > 0; o >>= 1) v += __shfl_down_sync(~0u, v, o);
        if (lane == 0) red[bb][wp] = v;
    }
    __syncthreads();
    if (tid < 8) {
        float v = 0.f;
        #pragma unroll
        for (int wpp = 0; wpp < 8; wpp++) v += red[tid][wpp];
        g_z[(bg * 8 + tid) * 30 + rr] = v + b[row];
    }
}

// ---------------- epilogue -------------------------------------------------------
__global__ void epilogue_k(float* __restrict__ out) {
    int idx = blockIdx.x * blockDim.x + threadIdx.x;
    if (idx >= BATCH * 12 * LEN) return;
    int b = idx / (12 * LEN);
    int rem = idx - b * 12 * LEN;
    int ch = rem / LEN;
    int p = rem - ch * LEN;
    int code = c_inv[ch];
    float v;
    if (code == -1) v = 0.f;
    else if (code == -2) v = 1.f;
    else {
        const float* z = &g_z[b * 30 + code * 5];
        if (p == 0) v = z[0];
        else if (p == 1) v = z[1];
        else if (p == 33) v = z[2];
        else if (p == 66) v = z[3];
        else if (p == 99) v = z[4];
        else {
            int j = p / 33;
            const int cl[3] = {1, 33, 66};
            float alpha = (float)(p - cl[j]) / 33.f;
            v = alpha * z[j + 1] + (1.f - alpha) * z[j + 2];
        }
    }
    out[idx] = v;
}

// ---------------- launcher ---------------------------------------------------------
extern "C" void kernel_launch(void* const* d_in, const int* in_sizes, int n_in,
                              void* d_out, int out_size) {
    const float* x       = (const float*)d_in[0];
    const float* conv1_w = (const float*)d_in[1];
    const float* conv1_b = (const float*)d_in[2];
    const float* bn1_g   = (const float*)d_in[3];
    const float* bn1_b   = (const float*)d_in[4];
    const float* conv2_w = (const float*)d_in[5];
    const float* conv2_b = (const float*)d_in[6];
    const float* bn2_g   = (const float*)d_in[7];
    const float* bn2_b   = (const float*)d_in[8];
    const float* conv3_w = (const float*)d_in[9];
    const float* conv3_b = (const float*)d_in[10];
    const float* bn3_g   = (const float*)d_in[11];
    const float* bn3_b   = (const float*)d_in[12];
    const float* fc1_w   = (const float*)d_in[13];
    const float* fc1_b   = (const float*)d_in[14];
    const float* bn4_g   = (const float*)d_in[15];
    const float* bn4_b   = (const float*)d_in[16];
    const float* fc2_w   = (const float*)d_in[17];
    const float* fc2_b   = (const float*)d_in[18];
    const float* bn5_g   = (const float*)d_in[19];
    const float* bn5_b   = (const float*)d_in[20];
    const float* fc3_w   = (const float*)d_in[21];
    const float* fc3_b   = (const float*)d_in[22];
    float* out = (float*)d_out;

    cudaFuncSetAttribute(gemm_tc, cudaFuncAttributeMaxDynamicSharedMemorySize, 2 * STG);

    conv1_k<<<BATCH, 256>>>(x, conv1_w, conv1_b);                                   // 1
    conv_k<<<dim3(BATCH, 8), 256>>>(1, 2, L1, (float)L1, conv2_w, conv2_b,
                                    bn1_g, bn1_b);                                  // 2
    conv_k<<<dim3(BATCH, 8), 256>>>(2, 3, L2S, (float)L2S, conv3_w, conv3_b,
                                    bn2_g, bn2_b);                                  // 3
    prep3_k<<<dim3(BATCH, 8), 256>>>(bn3_g, bn3_b);                                 // 4
    gemm_tc<<<dim3(125, 2), 320, 2 * STG>>>(fc1_w, KFC1, KP1, 94);                  // 5
    comb4_k<<<157, 256>>>(fc1_b, bn4_g, bn4_b);                                     // 6
    gemm_tc<<<dim3(125, 2), 320, 2 * STG>>>(fc2_w, HID, KP2, 157);                  // 7
    comb5_k<<<157, 256>>>(fc2_b, bn5_g, bn5_b);                                     // 8
    fc3_k<<<dim3(30, 8), 256>>>(fc3_w, fc3_b);                                      // 9
    epilogue_k<<<(BATCH * 12 * LEN + 255) / 256, 256>>>(out);                       // 10
}